// round 9
// baseline (speedup 1.0000x reference)
#include <cuda_runtime.h>
#include <cstdint>

#define Nn 50000
#define Ee 800000
#define Hh 128
#define Ll 4
#define Gg 64
#define NB 196   // (Nn+255)/256 scan blocks

// ---------------- scratch (device globals; no allocation allowed) ----------
__device__ float g_h[(size_t)Nn * Hh];     // node features (vn-added / post-MLP)
__device__ float g_agg[(size_t)Nn * Hh];   // mean-aggregated messages
__device__ float g_invdeg[Nn];
__device__ int   g_deg[Nn];
__device__ float g_vn[Gg * Hh];
__device__ float g_vt[Gg * Hh];
__device__ int   g_off[Nn + 1];
__device__ int   g_cursor[Nn];
__device__ int   g_bsum[256];
__device__ int   g_bpre[256];
__device__ float2 g_csr[Ee];               // {src_as_float, attr} grouped by tgt

// ---------------- degree histogram ------------------------------------------
__global__ void k_deg(const int* __restrict__ tgt) {
    int e = blockIdx.x * blockDim.x + threadIdx.x;
    if (e < Ee) atomicAdd(&g_deg[__ldg(tgt + e)], 1);
}

// ---------------- scan 1: block sums (+ vn init) ----------------------------
__global__ void k_scan1(const float* __restrict__ vn_emb) {
    __shared__ int s[256];
    int n = blockIdx.x * 256 + threadIdx.x;
    int d = (n < Nn) ? g_deg[n] : 0;
    s[threadIdx.x] = d;
    __syncthreads();
    for (int off = 128; off > 0; off >>= 1) {
        if (threadIdx.x < off) s[threadIdx.x] += s[threadIdx.x + off];
        __syncthreads();
    }
    if (threadIdx.x == 0) g_bsum[blockIdx.x] = s[0];
    if (n < Gg * Hh) g_vn[n] = __ldg(vn_emb + (n & (Hh - 1)));
}
__global__ void k_scan2() {
    __shared__ int s[256];
    int tid = threadIdx.x;
    int v = (tid < NB) ? g_bsum[tid] : 0;
    s[tid] = v;
    __syncthreads();
    for (int off = 1; off < 256; off <<= 1) {
        int t = (tid >= off) ? s[tid - off] : 0;
        __syncthreads();
        s[tid] += t;
        __syncthreads();
    }
    if (tid < NB) g_bpre[tid] = s[tid] - v;   // exclusive
}
__global__ void k_scan3() {
    __shared__ int s[256];
    int tid = threadIdx.x;
    int n = blockIdx.x * 256 + tid;
    int d = (n < Nn) ? g_deg[n] : 0;
    s[tid] = d;
    __syncthreads();
    for (int off = 1; off < 256; off <<= 1) {
        int t = (tid >= off) ? s[tid - off] : 0;
        __syncthreads();
        s[tid] += t;
        __syncthreads();
    }
    if (n < Nn) {
        int excl = s[tid] - d + g_bpre[blockIdx.x];
        g_off[n] = excl;
        g_cursor[n] = excl;
        g_invdeg[n] = 1.0f / (float)(d > 0 ? d : 1);
    }
    if (blockIdx.x == 0 && tid == 0) g_off[Nn] = Ee;
}

// ---------------- scatter edges into CSR buckets ----------------------------
__global__ void k_scatter(const int* __restrict__ ei,
                          const float* __restrict__ eattr) {
    int e = blockIdx.x * blockDim.x + threadIdx.x;
    if (e >= Ee) return;
    int s = __ldg(ei + e);
    int t = __ldg(ei + Ee + e);
    int p = atomicAdd(&g_cursor[t], 1);
    g_csr[p] = make_float2(__int_as_float(s), __ldg(eattr + e));
}

// ---------------- h = src + vn[batch]  (once per node) ----------------------
__global__ void k_addvn(const float* __restrict__ xin,
                        const int* __restrict__ batch, int use_x) {
    int i = blockIdx.x * blockDim.x + threadIdx.x;
    if (i >= Nn * 32) return;
    int n = i >> 5;
    int q = (i & 31) * 4;
    const float* srcp = use_x ? xin : g_h;
    int b = __ldg(batch + n);
    float4 v = *(const float4*)(srcp + (size_t)n * Hh + q);
    float4 w = *(const float4*)(g_vn + b * Hh + q);
    v.x += w.x; v.y += w.y; v.z += w.z; v.w += w.w;
    *(float4*)(g_h + (size_t)n * Hh + q) = v;
}

// ---------------- CSR mean aggregation: one warp per node -------------------
__device__ __forceinline__ void msg_acc(float4& acc, const float4 h4, float a,
                                        const float4 w, const float4 bb) {
    acc.x += fmaxf(h4.x + fmaf(a, w.x, bb.x), 0.0f);
    acc.y += fmaxf(h4.y + fmaf(a, w.y, bb.y), 0.0f);
    acc.z += fmaxf(h4.z + fmaf(a, w.z, bb.z), 0.0f);
    acc.w += fmaxf(h4.w + fmaf(a, w.w, bb.w), 0.0f);
}

__global__ void k_agg(const float* __restrict__ eW,
                      const float* __restrict__ eb) {
    int n = (blockIdx.x * blockDim.x + threadIdx.x) >> 5;
    if (n >= Nn) return;
    int lane = threadIdx.x & 31;
    int q = lane * 4;
    float4 w  = *(const float4*)(eW + q);
    float4 bb = *(const float4*)(eb + q);
    int j0 = g_off[n], j1 = g_off[n + 1];
    float4 acc = make_float4(0.f, 0.f, 0.f, 0.f);
    int j = j0;
    for (; j + 4 <= j1; j += 4) {
        float2 e0 = __ldg(&g_csr[j + 0]);
        float2 e1 = __ldg(&g_csr[j + 1]);
        float2 e2 = __ldg(&g_csr[j + 2]);
        float2 e3 = __ldg(&g_csr[j + 3]);
        float4 h0 = *(const float4*)(g_h + (size_t)__float_as_int(e0.x) * Hh + q);
        float4 h1 = *(const float4*)(g_h + (size_t)__float_as_int(e1.x) * Hh + q);
        float4 h2 = *(const float4*)(g_h + (size_t)__float_as_int(e2.x) * Hh + q);
        float4 h3 = *(const float4*)(g_h + (size_t)__float_as_int(e3.x) * Hh + q);
        msg_acc(acc, h0, e0.y, w, bb);
        msg_acc(acc, h1, e1.y, w, bb);
        msg_acc(acc, h2, e2.y, w, bb);
        msg_acc(acc, h3, e3.y, w, bb);
    }
    for (; j < j1; j++) {
        float2 e0 = __ldg(&g_csr[j]);
        float4 h0 = *(const float4*)(g_h + (size_t)__float_as_int(e0.x) * Hh + q);
        msg_acc(acc, h0, e0.y, w, bb);
    }
    float idg = g_invdeg[n];
    acc.x *= idg; acc.y *= idg; acc.z *= idg; acc.w *= idg;
    *(float4*)(g_agg + (size_t)n * Hh + q) = acc;
}

// ================= fused 2-GEMM MLP (3xTF32 split, mma.sync) ================
// C1 = relu(((1+eps)h + agg) @ W1 + b1)   kept in SMEM fp32
// h  = C1 @ W2 + b2  -> g_h and JK output block
#define KCH  32
#define PADA 36    // A-frag LDS conflict-free
#define PADB 136   // B-frag LDS conflict-free
#define PADC 132   // C1 fp32 tile; (4r + c) % 32 distinct per warp frag

__device__ __forceinline__ uint32_t to_tf32(float z) {
    uint32_t h;
    asm("cvt.rna.tf32.f32 %0, %1;" : "=r"(h) : "f"(z));
    return h;
}
__device__ __forceinline__ void split_tf32(float z, float& hi, float& lo) {
    uint32_t h = to_tf32(z);
    hi = __uint_as_float(h);
    lo = __uint_as_float(to_tf32(z - hi));
}

#define MMA_TF32(d, a, b0_, b1_) \
    asm volatile("mma.sync.aligned.m16n8k8.row.col.f32.tf32.tf32.f32 " \
        "{%0,%1,%2,%3}, {%4,%5,%6,%7}, {%8,%9}, {%0,%1,%2,%3};" \
        : "+f"((d)[0]), "+f"((d)[1]), "+f"((d)[2]), "+f"((d)[3]) \
        : "r"((a)[0]), "r"((a)[1]), "r"((a)[2]), "r"((a)[3]), \
          "r"(b0_), "r"(b1_))

// stage one K-chunk of a weight matrix as hi/lo into Bhs/Bls
__device__ __forceinline__ void stage_B(const float* __restrict__ W, int K0,
                                        float* Bhs, float* Bls, int tid) {
    int n4 = (tid & 31) * 4;
    int kb = tid >> 5;
    #pragma unroll
    for (int i = 0; i < 4; i++) {
        int kk = kb + i * 8;
        float4 w = *(const float4*)(W + (size_t)(K0 + kk) * Hh + n4);
        float4 hi, lo;
        split_tf32(w.x, hi.x, lo.x);
        split_tf32(w.y, hi.y, lo.y);
        split_tf32(w.z, hi.z, lo.z);
        split_tf32(w.w, hi.w, lo.w);
        *(float4*)&Bhs[kk * PADB + n4] = hi;
        *(float4*)&Bls[kk * PADB + n4] = lo;
    }
}

__global__ void __launch_bounds__(256, 2)
k_mlp(const float* __restrict__ epsPtr,
      const float* __restrict__ W1, const float* __restrict__ b1,
      const float* __restrict__ W2, const float* __restrict__ b2,
      float* __restrict__ C2, int c2off) {
    extern __shared__ float sm[];
    float* Bhs = sm;                         // [KCH][PADB]
    float* Bls = Bhs + KCH * PADB;
    float* U   = Bls + KCH * PADB;           // union region
    float* Ahs = U;                          // [128][PADA]  (GEMM1 staging)
    float* Als = U + 128 * PADA;
    float* C1s = U;                          // [128][PADC]  (after GEMM1)
    __shared__ float sb1[128], sb2[128];

    int tid = threadIdx.x;
    if (tid < 128) { sb1[tid] = __ldg(b1 + tid); sb2[tid] = __ldg(b2 + tid); }

    int row0 = blockIdx.x * 128;
    int warp = tid >> 5, lane = tid & 31;
    int m_block = warp >> 1;
    int n_block = warp & 1;
    int g2 = lane >> 2, t4 = lane & 3;

    int sr = tid >> 1;
    int sks = (tid & 1) * 16;
    int grow_s = row0 + sr;
    bool valid_s = grow_s < Nn;
    float ep = 1.0f + __ldg(epsPtr);

    float acc[2][8][4];
    #pragma unroll
    for (int mt = 0; mt < 2; mt++)
        #pragma unroll
        for (int nt = 0; nt < 8; nt++)
            #pragma unroll
            for (int q = 0; q < 4; q++) acc[mt][nt][q] = 0.0f;

    // ================= GEMM1: C1 = relu(((1+eps)h + agg) @ W1 + b1) ========
    #pragma unroll 1
    for (int c = 0; c < 4; c++) {
        int K0 = c * KCH;
        __syncthreads();
        {   // stage A chunk hi/lo
            const float* Ar = g_h + (size_t)grow_s * Hh + K0 + sks;
            const float* Gr = g_agg + (size_t)grow_s * Hh + K0 + sks;
            #pragma unroll
            for (int kk = 0; kk < 16; kk += 4) {
                float4 v = make_float4(0.f, 0.f, 0.f, 0.f);
                if (valid_s) {
                    v = *(const float4*)(Ar + kk);
                    float4 a4 = *(const float4*)(Gr + kk);
                    v.x = fmaf(ep, v.x, a4.x);
                    v.y = fmaf(ep, v.y, a4.y);
                    v.z = fmaf(ep, v.z, a4.z);
                    v.w = fmaf(ep, v.w, a4.w);
                }
                float4 hi, lo;
                split_tf32(v.x, hi.x, lo.x);
                split_tf32(v.y, hi.y, lo.y);
                split_tf32(v.z, hi.z, lo.z);
                split_tf32(v.w, hi.w, lo.w);
                *(float4*)&Ahs[sr * PADA + sks + kk] = hi;
                *(float4*)&Als[sr * PADA + sks + kk] = lo;
            }
        }
        stage_B(W1, K0, Bhs, Bls, tid);
        __syncthreads();
        #pragma unroll
        for (int k8 = 0; k8 < 4; k8++) {
            uint32_t ah[2][4], al[2][4];
            #pragma unroll
            for (int mt = 0; mt < 2; mt++) {
                int r = m_block * 32 + mt * 16 + g2;
                int col = k8 * 8 + t4;
                ah[mt][0] = __float_as_uint(Ahs[r * PADA + col]);
                ah[mt][1] = __float_as_uint(Ahs[(r + 8) * PADA + col]);
                ah[mt][2] = __float_as_uint(Ahs[r * PADA + col + 4]);
                ah[mt][3] = __float_as_uint(Ahs[(r + 8) * PADA + col + 4]);
                al[mt][0] = __float_as_uint(Als[r * PADA + col]);
                al[mt][1] = __float_as_uint(Als[(r + 8) * PADA + col]);
                al[mt][2] = __float_as_uint(Als[r * PADA + col + 4]);
                al[mt][3] = __float_as_uint(Als[(r + 8) * PADA + col + 4]);
            }
            #pragma unroll
            for (int nt = 0; nt < 8; nt++) {
                int bn = n_block * 64 + nt * 8 + g2;
                int bk = k8 * 8 + t4;
                uint32_t bh0 = __float_as_uint(Bhs[bk * PADB + bn]);
                uint32_t bh1 = __float_as_uint(Bhs[(bk + 4) * PADB + bn]);
                uint32_t bl0 = __float_as_uint(Bls[bk * PADB + bn]);
                uint32_t bl1 = __float_as_uint(Bls[(bk + 4) * PADB + bn]);
                #pragma unroll
                for (int mt = 0; mt < 2; mt++) {
                    MMA_TF32(acc[mt][nt], ah[mt], bh0, bh1);
                    MMA_TF32(acc[mt][nt], al[mt], bh0, bh1);
                    MMA_TF32(acc[mt][nt], ah[mt], bl0, bl1);
                }
            }
        }
    }

    // ---- write C1 = relu(acc + b1) into SMEM fp32 tile ----
    __syncthreads();   // all GEMM1 smem reads done; U region being repurposed
    #pragma unroll
    for (int mt = 0; mt < 2; mt++) {
        int r_lo = m_block * 32 + mt * 16 + g2;
        #pragma unroll
        for (int nt = 0; nt < 8; nt++) {
            int cc = n_block * 64 + nt * 8 + t4 * 2;
            float b0 = sb1[cc], b1v = sb1[cc + 1];
            C1s[r_lo * PADC + cc]       = fmaxf(acc[mt][nt][0] + b0, 0.f);
            C1s[r_lo * PADC + cc + 1]   = fmaxf(acc[mt][nt][1] + b1v, 0.f);
            C1s[(r_lo + 8) * PADC + cc]     = fmaxf(acc[mt][nt][2] + b0, 0.f);
            C1s[(r_lo + 8) * PADC + cc + 1] = fmaxf(acc[mt][nt][3] + b1v, 0.f);
        }
    }

    // ================= GEMM2: h = C1 @ W2 + b2 ==============================
    #pragma unroll
    for (int mt = 0; mt < 2; mt++)
        #pragma unroll
        for (int nt = 0; nt < 8; nt++)
            #pragma unroll
            for (int q = 0; q < 4; q++) acc[mt][nt][q] = 0.0f;

    #pragma unroll 1
    for (int c = 0; c < 4; c++) {
        int K0 = c * KCH;
        __syncthreads();   // prior chunk B reads done / C1 writes visible
        stage_B(W2, K0, Bhs, Bls, tid);
        __syncthreads();
        #pragma unroll
        for (int k8 = 0; k8 < 4; k8++) {
            uint32_t ah[2][4], al[2][4];
            #pragma unroll
            for (int mt = 0; mt < 2; mt++) {
                int r = m_block * 32 + mt * 16 + g2;
                int col = K0 + k8 * 8 + t4;
                float v0 = C1s[r * PADC + col];
                float v1 = C1s[(r + 8) * PADC + col];
                float v2 = C1s[r * PADC + col + 4];
                float v3 = C1s[(r + 8) * PADC + col + 4];
                float h0, l0, h1, l1, h2, l2, h3, l3;
                split_tf32(v0, h0, l0);
                split_tf32(v1, h1, l1);
                split_tf32(v2, h2, l2);
                split_tf32(v3, h3, l3);
                ah[mt][0] = __float_as_uint(h0); al[mt][0] = __float_as_uint(l0);
                ah[mt][1] = __float_as_uint(h1); al[mt][1] = __float_as_uint(l1);
                ah[mt][2] = __float_as_uint(h2); al[mt][2] = __float_as_uint(l2);
                ah[mt][3] = __float_as_uint(h3); al[mt][3] = __float_as_uint(l3);
            }
            #pragma unroll
            for (int nt = 0; nt < 8; nt++) {
                int bn = n_block * 64 + nt * 8 + g2;
                int bk = k8 * 8 + t4;
                uint32_t bh0 = __float_as_uint(Bhs[bk * PADB + bn]);
                uint32_t bh1 = __float_as_uint(Bhs[(bk + 4) * PADB + bn]);
                uint32_t bl0 = __float_as_uint(Bls[bk * PADB + bn]);
                uint32_t bl1 = __float_as_uint(Bls[(bk + 4) * PADB + bn]);
                #pragma unroll
                for (int mt = 0; mt < 2; mt++) {
                    MMA_TF32(acc[mt][nt], ah[mt], bh0, bh1);
                    MMA_TF32(acc[mt][nt], al[mt], bh0, bh1);
                    MMA_TF32(acc[mt][nt], ah[mt], bl0, bl1);
                }
            }
        }
    }

    // ---- epilogue: g_h and JK block ----
    #pragma unroll
    for (int mt = 0; mt < 2; mt++) {
        int r_lo = row0 + m_block * 32 + mt * 16 + g2;
        int r_hi = r_lo + 8;
        #pragma unroll
        for (int nt = 0; nt < 8; nt++) {
            int cc = n_block * 64 + nt * 8 + t4 * 2;
            float b0 = sb2[cc], b1v = sb2[cc + 1];
            float2 o0 = make_float2(acc[mt][nt][0] + b0, acc[mt][nt][1] + b1v);
            float2 o1 = make_float2(acc[mt][nt][2] + b0, acc[mt][nt][3] + b1v);
            if (r_lo < Nn) {
                *(float2*)(g_h + (size_t)r_lo * Hh + cc) = o0;
                *(float2*)(C2 + (size_t)r_lo * (Ll * Hh) + c2off + cc) = o0;
            }
            if (r_hi < Nn) {
                *(float2*)(g_h + (size_t)r_hi * Hh + cc) = o1;
                *(float2*)(C2 + (size_t)r_hi * (Ll * Hh) + c2off + cc) = o1;
            }
        }
    }
}

// ---------------- vt: init + parallel partial sums --------------------------
__global__ void k_vtinit() {
    int i = blockIdx.x * blockDim.x + threadIdx.x;
    if (i < Gg * Hh) g_vt[i] = g_vn[i];
}

__global__ void k_vtadd(const int* __restrict__ batch) {
    int row0 = blockIdx.x * 128;
    int c = threadIdx.x;
    int end = row0 + 128; if (end > Nn) end = Nn;
    if (row0 >= Nn) return;
    int gfirst = __ldg(batch + row0);
    int glast  = __ldg(batch + end - 1);
    if (gfirst == glast) {
        float acc = 0.0f;
        #pragma unroll 4
        for (int n = row0; n < end; n++) acc += g_h[(size_t)n * Hh + c];
        atomicAdd(&g_vt[gfirst * Hh + c], acc);
    } else {
        float acc = 0.0f;
        int cur = gfirst;
        for (int n = row0; n < end; n++) {
            int g = __ldg(batch + n);
            if (g != cur) {
                atomicAdd(&g_vt[cur * Hh + c], acc);
                cur = g; acc = 0.0f;
            }
            acc += g_h[(size_t)n * Hh + c];
        }
        atomicAdd(&g_vt[cur * Hh + c], acc);
    }
}

// ---------------- virtual-node two-layer MLP (fused) ------------------------
__global__ void k_vnmlp(const float* __restrict__ W1, const float* __restrict__ b1,
                        const float* __restrict__ W2, const float* __restrict__ b2) {
    __shared__ float vrow[128];
    __shared__ float trow[128];
    int g = blockIdx.x, c = threadIdx.x;
    vrow[c] = g_vt[g * Hh + c];
    __syncthreads();
    float acc = __ldg(b1 + c);
    #pragma unroll 8
    for (int k = 0; k < 128; k++) acc = fmaf(vrow[k], __ldg(W1 + k * 128 + c), acc);
    trow[c] = fmaxf(acc, 0.0f);
    __syncthreads();
    float acc2 = __ldg(b2 + c);
    #pragma unroll 8
    for (int k = 0; k < 128; k++) acc2 = fmaf(trow[k], __ldg(W2 + k * 128 + c), acc2);
    g_vn[g * Hh + c] = fmaxf(acc2, 0.0f);
}

// ---------------- launcher ---------------------------------------------------
extern "C" void kernel_launch(void* const* d_in, const int* in_sizes, int n_in,
                              void* d_out, int out_size) {
    const float* x         = (const float*)d_in[0];
    const float* edge_attr = (const float*)d_in[1];
    const float* conv_W1   = (const float*)d_in[2];
    const float* conv_b1   = (const float*)d_in[3];
    const float* conv_W2   = (const float*)d_in[4];
    const float* conv_b2   = (const float*)d_in[5];
    const float* conv_eps  = (const float*)d_in[6];
    const float* edge_W    = (const float*)d_in[7];
    const float* edge_b    = (const float*)d_in[8];
    const float* vn_W1     = (const float*)d_in[9];
    const float* vn_b1     = (const float*)d_in[10];
    const float* vn_W2     = (const float*)d_in[11];
    const float* vn_b2     = (const float*)d_in[12];
    const float* vn_emb    = (const float*)d_in[13];
    const int*   edge_index= (const int*)d_in[14];
    const int*   batch     = (const int*)d_in[15];
    float* out = (float*)d_out;

    (void)in_sizes; (void)n_in; (void)out_size;

    void* p_deg = nullptr;
    cudaGetSymbolAddress(&p_deg, g_deg);

    // smem: B hi/lo (2*KCH*PADB) + union(max(A hi/lo, C1 tile))
    const int smem_floats =
        2 * KCH * PADB +
        ((2 * 128 * PADA > 128 * PADC) ? 2 * 128 * PADA : 128 * PADC);
    const int smem_bytes = smem_floats * (int)sizeof(float);
    cudaFuncSetAttribute(k_mlp, cudaFuncAttributeMaxDynamicSharedMemorySize,
                         smem_bytes);

    // ---- CSR build ----
    cudaMemsetAsync(p_deg, 0, Nn * sizeof(int), 0);
    k_deg<<<(Ee + 255) / 256, 256>>>(edge_index + Ee);
    k_scan1<<<NB, 256>>>(vn_emb);
    k_scan2<<<1, 256>>>();
    k_scan3<<<NB, 256>>>();
    k_scatter<<<(Ee + 255) / 256, 256>>>(edge_index, edge_attr);

    const int agg_grid  = (Nn * 32 + 255) / 256;
    const int gemm_grid = (Nn + 127) / 128;

    for (int i = 0; i < Ll; i++) {
        k_addvn<<<(Nn * 32 + 255) / 256, 256>>>(x, batch, i == 0 ? 1 : 0);
        k_agg<<<agg_grid, 256>>>(edge_W + i * Hh, edge_b + i * Hh);
        k_mlp<<<gemm_grid, 256, smem_bytes>>>(conv_eps + i,
                                              conv_W1 + (size_t)i * Hh * Hh,
                                              conv_b1 + i * Hh,
                                              conv_W2 + (size_t)i * Hh * Hh,
                                              conv_b2 + i * Hh, out, i * Hh);
        if (i < Ll - 1) {
            k_vtinit<<<(Gg * Hh + 255) / 256, 256>>>();
            k_vtadd<<<gemm_grid, 128>>>(batch);
            k_vnmlp<<<Gg, Hh>>>(vn_W1 + (size_t)i * Hh * Hh, vn_b1 + i * Hh,
                                vn_W2 + (size_t)i * Hh * Hh, vn_b2 + i * Hh);
        }
    }
}

// round 13
// speedup vs baseline: 1.3059x; 1.3059x over previous
#include <cuda_runtime.h>
#include <cstdint>

#define Nn 50000
#define Ee 800000
#define Hh 128
#define Ll 4
#define Gg 64
#define NB 196   // (Nn+255)/256 scan blocks

// ---------------- scratch (device globals; no allocation allowed) ----------
__device__ float  g_h[(size_t)Nn * Hh];    // node features (vn-added / post-MLP)
__device__ float  g_tmp[(size_t)Nn * Hh];  // MLP intermediate
__device__ float  g_agg[(size_t)Nn * Hh];  // mean-aggregated messages
__device__ float  g_invdeg[Nn];
__device__ int    g_deg[Nn];
__device__ float  g_vn[Gg * Hh];
__device__ float  g_vt[Gg * Hh];
__device__ int    g_off[Nn + 1];
__device__ int    g_cursor[Nn];
__device__ int    g_bsum[256];
__device__ int    g_bpre[256];
__device__ float2 g_csr[Ee];               // {src_as_float, attr} grouped by tgt

// ---------------- degree histogram ------------------------------------------
__global__ void k_deg(const int* __restrict__ tgt) {
    int e = blockIdx.x * blockDim.x + threadIdx.x;
    if (e < Ee) atomicAdd(&g_deg[__ldg(tgt + e)], 1);
}

// ---------------- scan 1: block sums (+ vn init) ----------------------------
__global__ void k_scan1(const float* __restrict__ vn_emb) {
    __shared__ int s[256];
    int n = blockIdx.x * 256 + threadIdx.x;
    int d = (n < Nn) ? g_deg[n] : 0;
    s[threadIdx.x] = d;
    __syncthreads();
    for (int off = 128; off > 0; off >>= 1) {
        if (threadIdx.x < off) s[threadIdx.x] += s[threadIdx.x + off];
        __syncthreads();
    }
    if (threadIdx.x == 0) g_bsum[blockIdx.x] = s[0];
    if (n < Gg * Hh) g_vn[n] = __ldg(vn_emb + (n & (Hh - 1)));
}
__global__ void k_scan2() {
    __shared__ int s[256];
    int tid = threadIdx.x;
    int v = (tid < NB) ? g_bsum[tid] : 0;
    s[tid] = v;
    __syncthreads();
    for (int off = 1; off < 256; off <<= 1) {
        int t = (tid >= off) ? s[tid - off] : 0;
        __syncthreads();
        s[tid] += t;
        __syncthreads();
    }
    if (tid < NB) g_bpre[tid] = s[tid] - v;   // exclusive
}
__global__ void k_scan3() {
    __shared__ int s[256];
    int tid = threadIdx.x;
    int n = blockIdx.x * 256 + tid;
    int d = (n < Nn) ? g_deg[n] : 0;
    s[tid] = d;
    __syncthreads();
    for (int off = 1; off < 256; off <<= 1) {
        int t = (tid >= off) ? s[tid - off] : 0;
        __syncthreads();
        s[tid] += t;
        __syncthreads();
    }
    if (n < Nn) {
        int excl = s[tid] - d + g_bpre[blockIdx.x];
        g_off[n] = excl;
        g_cursor[n] = excl;
        g_invdeg[n] = 1.0f / (float)(d > 0 ? d : 1);
    }
    if (blockIdx.x == 0 && tid == 0) g_off[Nn] = Ee;
}

// ---------------- scatter edges into CSR buckets ----------------------------
__global__ void k_scatter(const int* __restrict__ ei,
                          const float* __restrict__ eattr) {
    int e = blockIdx.x * blockDim.x + threadIdx.x;
    if (e >= Ee) return;
    int s = __ldg(ei + e);
    int t = __ldg(ei + Ee + e);
    int p = atomicAdd(&g_cursor[t], 1);
    g_csr[p] = make_float2(__int_as_float(s), __ldg(eattr + e));
}

// ---------------- h = src + vn[batch]  (once per node) ----------------------
__global__ void k_addvn(const float* __restrict__ xin,
                        const int* __restrict__ batch, int use_x) {
    int i = blockIdx.x * blockDim.x + threadIdx.x;
    if (i >= Nn * 32) return;
    int n = i >> 5;
    int q = (i & 31) * 4;
    const float* srcp = use_x ? xin : g_h;
    int b = __ldg(batch + n);
    float4 v = *(const float4*)(srcp + (size_t)n * Hh + q);
    float4 w = *(const float4*)(g_vn + b * Hh + q);
    v.x += w.x; v.y += w.y; v.z += w.z; v.w += w.w;
    *(float4*)(g_h + (size_t)n * Hh + q) = v;
}

// ---------------- CSR mean aggregation: one warp per node -------------------
__device__ __forceinline__ void msg_acc(float4& acc, const float4 h4, float a,
                                        const float4 w, const float4 bb) {
    acc.x += fmaxf(h4.x + fmaf(a, w.x, bb.x), 0.0f);
    acc.y += fmaxf(h4.y + fmaf(a, w.y, bb.y), 0.0f);
    acc.z += fmaxf(h4.z + fmaf(a, w.z, bb.z), 0.0f);
    acc.w += fmaxf(h4.w + fmaf(a, w.w, bb.w), 0.0f);
}

__global__ void k_agg(const float* __restrict__ eW,
                      const float* __restrict__ eb) {
    int n = (blockIdx.x * blockDim.x + threadIdx.x) >> 5;
    if (n >= Nn) return;
    int lane = threadIdx.x & 31;
    int q = lane * 4;
    float4 w  = *(const float4*)(eW + q);
    float4 bb = *(const float4*)(eb + q);
    int j0 = g_off[n], j1 = g_off[n + 1];
    float4 acc = make_float4(0.f, 0.f, 0.f, 0.f);
    int j = j0;
    for (; j + 4 <= j1; j += 4) {
        float2 e0 = __ldg(&g_csr[j + 0]);
        float2 e1 = __ldg(&g_csr[j + 1]);
        float2 e2 = __ldg(&g_csr[j + 2]);
        float2 e3 = __ldg(&g_csr[j + 3]);
        float4 h0 = *(const float4*)(g_h + (size_t)__float_as_int(e0.x) * Hh + q);
        float4 h1 = *(const float4*)(g_h + (size_t)__float_as_int(e1.x) * Hh + q);
        float4 h2 = *(const float4*)(g_h + (size_t)__float_as_int(e2.x) * Hh + q);
        float4 h3 = *(const float4*)(g_h + (size_t)__float_as_int(e3.x) * Hh + q);
        msg_acc(acc, h0, e0.y, w, bb);
        msg_acc(acc, h1, e1.y, w, bb);
        msg_acc(acc, h2, e2.y, w, bb);
        msg_acc(acc, h3, e3.y, w, bb);
    }
    for (; j < j1; j++) {
        float2 e0 = __ldg(&g_csr[j]);
        float4 h0 = *(const float4*)(g_h + (size_t)__float_as_int(e0.x) * Hh + q);
        msg_acc(acc, h0, e0.y, w, bb);
    }
    float idg = g_invdeg[n];
    acc.x *= idg; acc.y *= idg; acc.z *= idg; acc.w *= idg;
    *(float4*)(g_agg + (size_t)n * Hh + q) = acc;
}

// ================= 3xTF32 split GEMM via mma.sync (R4 exact) ================
// K staged in 4 chunks of 32, B staged per chunk. 71.7KB smem -> 2 CTAs/SM.
// phase 0: A = (1+eps)*h + agg, C = relu(A@W1+b1) -> g_tmp
// phase 1: A = g_tmp, C = A@W2+b2 -> g_h and JK output block
#define KCH  32
#define PADA 36    // conflict-free A frag LDS
#define PADB 136   // conflict-free B frag LDS

__device__ __forceinline__ uint32_t to_tf32(float z) {
    uint32_t h;
    asm("cvt.rna.tf32.f32 %0, %1;" : "=r"(h) : "f"(z));
    return h;
}
__device__ __forceinline__ void split_tf32(float z, float& hi, float& lo) {
    uint32_t h = to_tf32(z);
    hi = __uint_as_float(h);
    lo = __uint_as_float(to_tf32(z - hi));
}

#define MMA_TF32(d, a, b0_, b1_) \
    asm volatile("mma.sync.aligned.m16n8k8.row.col.f32.tf32.tf32.f32 " \
        "{%0,%1,%2,%3}, {%4,%5,%6,%7}, {%8,%9}, {%0,%1,%2,%3};" \
        : "+f"((d)[0]), "+f"((d)[1]), "+f"((d)[2]), "+f"((d)[3]) \
        : "r"((a)[0]), "r"((a)[1]), "r"((a)[2]), "r"((a)[3]), \
          "r"(b0_), "r"(b1_))

__global__ void __launch_bounds__(256, 2)
k_gemm(int phase, const float* __restrict__ epsPtr,
       const float* __restrict__ W, const float* __restrict__ bias,
       float* __restrict__ C2, int c2off) {
    extern __shared__ float sm[];
    float* Ahs = sm;                       // [128][PADA]
    float* Als = Ahs + 128 * PADA;
    float* Bhs = Als + 128 * PADA;         // [KCH][PADB]
    float* Bls = Bhs + KCH * PADB;
    __shared__ float sbias[128];

    int tid = threadIdx.x;
    if (tid < 128) sbias[tid] = __ldg(bias + tid);

    int row0 = blockIdx.x * 128;
    int warp = tid >> 5, lane = tid & 31;
    int m_block = warp >> 1;
    int n_block = warp & 1;
    int g2 = lane >> 2, t4 = lane & 3;

    int sr = tid >> 1;
    int sks = (tid & 1) * 16;
    int grow_s = row0 + sr;
    bool valid_s = grow_s < Nn;
    float ep = 1.0f;
    if (phase == 0) ep = 1.0f + __ldg(epsPtr);
    const float* Asrc = phase ? g_tmp : g_h;

    float acc[2][8][4];
    #pragma unroll
    for (int mt = 0; mt < 2; mt++)
        #pragma unroll
        for (int nt = 0; nt < 8; nt++)
            #pragma unroll
            for (int q = 0; q < 4; q++) acc[mt][nt][q] = 0.0f;

    #pragma unroll 1
    for (int c = 0; c < 4; c++) {
        int K0 = c * KCH;
        __syncthreads();
        // ---- stage A hi/lo (fused (1+eps)h + agg in phase 0) ----
        {
            const float* Ar = Asrc + (size_t)grow_s * Hh + K0 + sks;
            const float* Gr = g_agg + (size_t)grow_s * Hh + K0 + sks;
            #pragma unroll
            for (int kk = 0; kk < 16; kk += 4) {
                float4 v = make_float4(0.f, 0.f, 0.f, 0.f);
                if (valid_s) {
                    v = *(const float4*)(Ar + kk);
                    if (phase == 0) {
                        float4 a4 = *(const float4*)(Gr + kk);
                        v.x = fmaf(ep, v.x, a4.x);
                        v.y = fmaf(ep, v.y, a4.y);
                        v.z = fmaf(ep, v.z, a4.z);
                        v.w = fmaf(ep, v.w, a4.w);
                    }
                }
                float4 hi, lo;
                split_tf32(v.x, hi.x, lo.x);
                split_tf32(v.y, hi.y, lo.y);
                split_tf32(v.z, hi.z, lo.z);
                split_tf32(v.w, hi.w, lo.w);
                *(float4*)&Ahs[sr * PADA + sks + kk] = hi;
                *(float4*)&Als[sr * PADA + sks + kk] = lo;
            }
        }
        // ---- stage B hi/lo: W rows K0..K0+31 ----
        {
            int n4 = (tid & 31) * 4;
            int kb = tid >> 5;
            #pragma unroll
            for (int i = 0; i < 4; i++) {
                int kk = kb + i * 8;
                float4 w = *(const float4*)(W + (size_t)(K0 + kk) * Hh + n4);
                float4 hi, lo;
                split_tf32(w.x, hi.x, lo.x);
                split_tf32(w.y, hi.y, lo.y);
                split_tf32(w.z, hi.z, lo.z);
                split_tf32(w.w, hi.w, lo.w);
                *(float4*)&Bhs[kk * PADB + n4] = hi;
                *(float4*)&Bls[kk * PADB + n4] = lo;
            }
        }
        __syncthreads();
        // ---- compute ----
        #pragma unroll
        for (int k8 = 0; k8 < 4; k8++) {
            uint32_t ah[2][4], al[2][4];
            #pragma unroll
            for (int mt = 0; mt < 2; mt++) {
                int r = m_block * 32 + mt * 16 + g2;
                int col = k8 * 8 + t4;
                ah[mt][0] = __float_as_uint(Ahs[r * PADA + col]);
                ah[mt][1] = __float_as_uint(Ahs[(r + 8) * PADA + col]);
                ah[mt][2] = __float_as_uint(Ahs[r * PADA + col + 4]);
                ah[mt][3] = __float_as_uint(Ahs[(r + 8) * PADA + col + 4]);
                al[mt][0] = __float_as_uint(Als[r * PADA + col]);
                al[mt][1] = __float_as_uint(Als[(r + 8) * PADA + col]);
                al[mt][2] = __float_as_uint(Als[r * PADA + col + 4]);
                al[mt][3] = __float_as_uint(Als[(r + 8) * PADA + col + 4]);
            }
            #pragma unroll
            for (int nt = 0; nt < 8; nt++) {
                int bn = n_block * 64 + nt * 8 + g2;
                int bk = k8 * 8 + t4;
                uint32_t bh0 = __float_as_uint(Bhs[bk * PADB + bn]);
                uint32_t bh1 = __float_as_uint(Bhs[(bk + 4) * PADB + bn]);
                uint32_t bl0 = __float_as_uint(Bls[bk * PADB + bn]);
                uint32_t bl1 = __float_as_uint(Bls[(bk + 4) * PADB + bn]);
                #pragma unroll
                for (int mt = 0; mt < 2; mt++) {
                    MMA_TF32(acc[mt][nt], ah[mt], bh0, bh1);
                    MMA_TF32(acc[mt][nt], al[mt], bh0, bh1);
                    MMA_TF32(acc[mt][nt], ah[mt], bl0, bl1);
                }
            }
        }
    }

    // ---- epilogue ----
    float* Cp = phase ? g_h : g_tmp;
    int do_relu = (phase == 0);
    #pragma unroll
    for (int mt = 0; mt < 2; mt++) {
        int r_lo = row0 + m_block * 32 + mt * 16 + g2;
        int r_hi = r_lo + 8;
        #pragma unroll
        for (int nt = 0; nt < 8; nt++) {
            int cc = n_block * 64 + nt * 8 + t4 * 2;
            float b0 = sbias[cc], b1 = sbias[cc + 1];
            float2 o0 = make_float2(acc[mt][nt][0] + b0, acc[mt][nt][1] + b1);
            float2 o1 = make_float2(acc[mt][nt][2] + b0, acc[mt][nt][3] + b1);
            if (do_relu) {
                o0.x = fmaxf(o0.x, 0.f); o0.y = fmaxf(o0.y, 0.f);
                o1.x = fmaxf(o1.x, 0.f); o1.y = fmaxf(o1.y, 0.f);
            }
            if (r_lo < Nn) {
                *(float2*)(Cp + (size_t)r_lo * Hh + cc) = o0;
                if (C2) *(float2*)(C2 + (size_t)r_lo * (Ll * Hh) + c2off + cc) = o0;
            }
            if (r_hi < Nn) {
                *(float2*)(Cp + (size_t)r_hi * Hh + cc) = o1;
                if (C2) *(float2*)(C2 + (size_t)r_hi * (Ll * Hh) + c2off + cc) = o1;
            }
        }
    }
}

// ---------------- vt: parallel partial sums (g_vt pre-zeroed) ---------------
__global__ void k_vtadd(const int* __restrict__ batch) {
    int row0 = blockIdx.x * 128;
    int c = threadIdx.x;
    int end = row0 + 128; if (end > Nn) end = Nn;
    if (row0 >= Nn) return;
    int gfirst = __ldg(batch + row0);
    int glast  = __ldg(batch + end - 1);
    if (gfirst == glast) {
        float acc = 0.0f;
        #pragma unroll 4
        for (int n = row0; n < end; n++) acc += g_h[(size_t)n * Hh + c];
        atomicAdd(&g_vt[gfirst * Hh + c], acc);
    } else {
        float acc = 0.0f;
        int cur = gfirst;
        for (int n = row0; n < end; n++) {
            int g = __ldg(batch + n);
            if (g != cur) {
                atomicAdd(&g_vt[cur * Hh + c], acc);
                cur = g; acc = 0.0f;
            }
            acc += g_h[(size_t)n * Hh + c];
        }
        atomicAdd(&g_vt[cur * Hh + c], acc);
    }
}

// ---------------- virtual-node two-layer MLP (vt + vn folded in) ------------
__global__ void k_vnmlp(const float* __restrict__ W1, const float* __restrict__ b1,
                        const float* __restrict__ W2, const float* __restrict__ b2) {
    __shared__ float vrow[128];
    __shared__ float trow[128];
    int g = blockIdx.x, c = threadIdx.x;
    vrow[c] = g_vt[g * Hh + c] + g_vn[g * Hh + c];
    __syncthreads();
    float acc = __ldg(b1 + c);
    #pragma unroll 8
    for (int k = 0; k < 128; k++) acc = fmaf(vrow[k], __ldg(W1 + k * 128 + c), acc);
    trow[c] = fmaxf(acc, 0.0f);
    __syncthreads();
    float acc2 = __ldg(b2 + c);
    #pragma unroll 8
    for (int k = 0; k < 128; k++) acc2 = fmaf(trow[k], __ldg(W2 + k * 128 + c), acc2);
    g_vn[g * Hh + c] = fmaxf(acc2, 0.0f);
}

// ---------------- launcher ---------------------------------------------------
extern "C" void kernel_launch(void* const* d_in, const int* in_sizes, int n_in,
                              void* d_out, int out_size) {
    const float* x         = (const float*)d_in[0];
    const float* edge_attr = (const float*)d_in[1];
    const float* conv_W1   = (const float*)d_in[2];
    const float* conv_b1   = (const float*)d_in[3];
    const float* conv_W2   = (const float*)d_in[4];
    const float* conv_b2   = (const float*)d_in[5];
    const float* conv_eps  = (const float*)d_in[6];
    const float* edge_W    = (const float*)d_in[7];
    const float* edge_b    = (const float*)d_in[8];
    const float* vn_W1     = (const float*)d_in[9];
    const float* vn_b1     = (const float*)d_in[10];
    const float* vn_W2     = (const float*)d_in[11];
    const float* vn_b2     = (const float*)d_in[12];
    const float* vn_emb    = (const float*)d_in[13];
    const int*   edge_index= (const int*)d_in[14];
    const int*   batch     = (const int*)d_in[15];
    float* out = (float*)d_out;

    (void)in_sizes; (void)n_in; (void)out_size;

    void* p_deg = nullptr;
    void* p_vt  = nullptr;
    cudaGetSymbolAddress(&p_deg, g_deg);
    cudaGetSymbolAddress(&p_vt, g_vt);

    const int smem_bytes =
        (2 * 128 * PADA + 2 * KCH * PADB) * (int)sizeof(float);
    cudaFuncSetAttribute(k_gemm, cudaFuncAttributeMaxDynamicSharedMemorySize,
                         smem_bytes);

    // ---- CSR build ----
    cudaMemsetAsync(p_deg, 0, Nn * sizeof(int), 0);
    k_deg<<<(Ee + 255) / 256, 256>>>(edge_index + Ee);
    k_scan1<<<NB, 256>>>(vn_emb);
    k_scan2<<<1, 256>>>();
    k_scan3<<<NB, 256>>>();
    k_scatter<<<(Ee + 255) / 256, 256>>>(edge_index, edge_attr);

    const int agg_grid  = (Nn * 32 + 255) / 256;
    const int gemm_grid = (Nn + 127) / 128;

    for (int i = 0; i < Ll; i++) {
        k_addvn<<<(Nn * 32 + 255) / 256, 256>>>(x, batch, i == 0 ? 1 : 0);
        k_agg<<<agg_grid, 256>>>(edge_W + i * Hh, edge_b + i * Hh);
        k_gemm<<<gemm_grid, 256, smem_bytes>>>(0, conv_eps + i,
                                               conv_W1 + (size_t)i * Hh * Hh,
                                               conv_b1 + i * Hh, nullptr, 0);
        k_gemm<<<gemm_grid, 256, smem_bytes>>>(1, conv_eps + i,
                                               conv_W2 + (size_t)i * Hh * Hh,
                                               conv_b2 + i * Hh, out, i * Hh);
        if (i < Ll - 1) {
            cudaMemsetAsync(p_vt, 0, Gg * Hh * sizeof(float), 0);
            k_vtadd<<<gemm_grid, 128>>>(batch);
            k_vnmlp<<<Gg, Hh>>>(vn_W1 + (size_t)i * Hh * Hh, vn_b1 + i * Hh,
                                vn_W2 + (size_t)i * Hh * Hh, vn_b2 + i * Hh);
        }
    }
}

// round 14
// speedup vs baseline: 1.3669x; 1.0467x over previous
#include <cuda_runtime.h>
#include <cstdint>

#define Nn 50000
#define Ee 800000
#define Hh 128
#define Ll 4
#define Gg 64
#define NB 196   // (Nn+255)/256 scan blocks

// ---------------- scratch (device globals; no allocation allowed) ----------
__device__ float  g_h[(size_t)Nn * Hh];    // node features (vn-added / post-MLP)
__device__ float  g_tmp[(size_t)Nn * Hh];  // MLP intermediate
__device__ float  g_agg[(size_t)Nn * Hh];  // mean-aggregated messages
__device__ float  g_invdeg[Nn];
__device__ int    g_deg[Nn];
__device__ float  g_vn[Gg * Hh];
__device__ float  g_vt[Gg * Hh];
__device__ int    g_off[Nn + 1];
__device__ int    g_cursor[Nn];
__device__ int    g_bsum[256];
__device__ int    g_bpre[256];
__device__ float2 g_csr[Ee];               // {src_as_float, attr} grouped by tgt

// ---------------- degree histogram ------------------------------------------
__global__ void k_deg(const int* __restrict__ tgt) {
    int e = blockIdx.x * blockDim.x + threadIdx.x;
    if (e < Ee) atomicAdd(&g_deg[__ldg(tgt + e)], 1);
}

// ---------------- scan 1: block sums (+ vn init) ----------------------------
__global__ void k_scan1(const float* __restrict__ vn_emb) {
    __shared__ int s[256];
    int n = blockIdx.x * 256 + threadIdx.x;
    int d = (n < Nn) ? g_deg[n] : 0;
    s[threadIdx.x] = d;
    __syncthreads();
    for (int off = 128; off > 0; off >>= 1) {
        if (threadIdx.x < off) s[threadIdx.x] += s[threadIdx.x + off];
        __syncthreads();
    }
    if (threadIdx.x == 0) g_bsum[blockIdx.x] = s[0];
    if (n < Gg * Hh) g_vn[n] = __ldg(vn_emb + (n & (Hh - 1)));
}
__global__ void k_scan2() {
    __shared__ int s[256];
    int tid = threadIdx.x;
    int v = (tid < NB) ? g_bsum[tid] : 0;
    s[tid] = v;
    __syncthreads();
    for (int off = 1; off < 256; off <<= 1) {
        int t = (tid >= off) ? s[tid - off] : 0;
        __syncthreads();
        s[tid] += t;
        __syncthreads();
    }
    if (tid < NB) g_bpre[tid] = s[tid] - v;   // exclusive
}
__global__ void k_scan3() {
    __shared__ int s[256];
    int tid = threadIdx.x;
    int n = blockIdx.x * 256 + tid;
    int d = (n < Nn) ? g_deg[n] : 0;
    s[tid] = d;
    __syncthreads();
    for (int off = 1; off < 256; off <<= 1) {
        int t = (tid >= off) ? s[tid - off] : 0;
        __syncthreads();
        s[tid] += t;
        __syncthreads();
    }
    if (n < Nn) {
        int excl = s[tid] - d + g_bpre[blockIdx.x];
        g_off[n] = excl;
        g_cursor[n] = excl;
        g_invdeg[n] = 1.0f / (float)(d > 0 ? d : 1);
    }
    if (blockIdx.x == 0 && tid == 0) g_off[Nn] = Ee;
}

// ---------------- scatter edges into CSR buckets ----------------------------
__global__ void k_scatter(const int* __restrict__ ei,
                          const float* __restrict__ eattr) {
    int e = blockIdx.x * blockDim.x + threadIdx.x;
    if (e >= Ee) return;
    int s = __ldg(ei + e);
    int t = __ldg(ei + Ee + e);
    int p = atomicAdd(&g_cursor[t], 1);
    g_csr[p] = make_float2(__int_as_float(s), __ldg(eattr + e));
}

// ---------------- h = src + vn[batch]  (once per node) ----------------------
__global__ void k_addvn(const float* __restrict__ xin,
                        const int* __restrict__ batch, int use_x) {
    int i = blockIdx.x * blockDim.x + threadIdx.x;
    if (i >= Nn * 32) return;
    int n = i >> 5;
    int q = (i & 31) * 4;
    const float* srcp = use_x ? xin : g_h;
    int b = __ldg(batch + n);
    float4 v = *(const float4*)(srcp + (size_t)n * Hh + q);
    float4 w = *(const float4*)(g_vn + b * Hh + q);
    v.x += w.x; v.y += w.y; v.z += w.z; v.w += w.w;
    *(float4*)(g_h + (size_t)n * Hh + q) = v;
}

// ---------------- CSR mean aggregation: one warp per node, unroll 8 ---------
__device__ __forceinline__ void msg_acc(float4& acc, const float4 h4, float a,
                                        const float4 w, const float4 bb) {
    acc.x += fmaxf(h4.x + fmaf(a, w.x, bb.x), 0.0f);
    acc.y += fmaxf(h4.y + fmaf(a, w.y, bb.y), 0.0f);
    acc.z += fmaxf(h4.z + fmaf(a, w.z, bb.z), 0.0f);
    acc.w += fmaxf(h4.w + fmaf(a, w.w, bb.w), 0.0f);
}

__global__ void k_agg(const float* __restrict__ eW,
                      const float* __restrict__ eb) {
    int n = (blockIdx.x * blockDim.x + threadIdx.x) >> 5;
    if (n >= Nn) return;
    int lane = threadIdx.x & 31;
    int q = lane * 4;
    float4 w  = *(const float4*)(eW + q);
    float4 bb = *(const float4*)(eb + q);
    int j0 = g_off[n], j1 = g_off[n + 1];
    float4 acc = make_float4(0.f, 0.f, 0.f, 0.f);
    int j = j0;
    for (; j + 8 <= j1; j += 8) {
        float2 e[8];
        #pragma unroll
        for (int u = 0; u < 8; u++) e[u] = __ldg(&g_csr[j + u]);
        float4 h[8];
        #pragma unroll
        for (int u = 0; u < 8; u++)
            h[u] = *(const float4*)(g_h + (size_t)__float_as_int(e[u].x) * Hh + q);
        #pragma unroll
        for (int u = 0; u < 8; u++) msg_acc(acc, h[u], e[u].y, w, bb);
    }
    for (; j < j1; j++) {
        float2 e0 = __ldg(&g_csr[j]);
        float4 h0 = *(const float4*)(g_h + (size_t)__float_as_int(e0.x) * Hh + q);
        msg_acc(acc, h0, e0.y, w, bb);
    }
    float idg = g_invdeg[n];
    acc.x *= idg; acc.y *= idg; acc.z *= idg; acc.w *= idg;
    *(float4*)(g_agg + (size_t)n * Hh + q) = acc;
}

// ================= 3xTF32 split GEMM via mma.sync ===========================
// K staged in 4 chunks of 32, B staged per chunk. 71.7KB smem -> 2 CTAs/SM.
// Chunk-c global loads PREFETCHED above the barrier (overlap with chunk c-1 MMA).
// phase 0: A = (1+eps)*h + agg, C = relu(A@W1+b1) -> g_tmp
// phase 1: A = g_tmp, C = A@W2+b2 -> g_h and JK output block
#define KCH  32
#define PADA 36    // conflict-free A frag LDS
#define PADB 136   // conflict-free B frag LDS

__device__ __forceinline__ uint32_t to_tf32(float z) {
    uint32_t h;
    asm("cvt.rna.tf32.f32 %0, %1;" : "=r"(h) : "f"(z));
    return h;
}
__device__ __forceinline__ void split_tf32(float z, float& hi, float& lo) {
    uint32_t h = to_tf32(z);
    hi = __uint_as_float(h);
    lo = __uint_as_float(to_tf32(z - hi));
}

#define MMA_TF32(d, a, b0_, b1_) \
    asm volatile("mma.sync.aligned.m16n8k8.row.col.f32.tf32.tf32.f32 " \
        "{%0,%1,%2,%3}, {%4,%5,%6,%7}, {%8,%9}, {%0,%1,%2,%3};" \
        : "+f"((d)[0]), "+f"((d)[1]), "+f"((d)[2]), "+f"((d)[3]) \
        : "r"((a)[0]), "r"((a)[1]), "r"((a)[2]), "r"((a)[3]), \
          "r"(b0_), "r"(b1_))

__global__ void __launch_bounds__(256, 2)
k_gemm(int phase, const float* __restrict__ epsPtr,
       const float* __restrict__ W, const float* __restrict__ bias,
       float* __restrict__ C2, int c2off) {
    extern __shared__ float sm[];
    float* Ahs = sm;                       // [128][PADA]
    float* Als = Ahs + 128 * PADA;
    float* Bhs = Als + 128 * PADA;         // [KCH][PADB]
    float* Bls = Bhs + KCH * PADB;
    __shared__ float sbias[128];

    int tid = threadIdx.x;
    if (tid < 128) sbias[tid] = __ldg(bias + tid);

    int row0 = blockIdx.x * 128;
    int warp = tid >> 5, lane = tid & 31;
    int m_block = warp >> 1;
    int n_block = warp & 1;
    int g2 = lane >> 2, t4 = lane & 3;

    int sr = tid >> 1;
    int sks = (tid & 1) * 16;
    int grow_s = row0 + sr;
    bool valid_s = grow_s < Nn;
    float ep = 1.0f;
    if (phase == 0) ep = 1.0f + __ldg(epsPtr);
    const float* Asrc = phase ? g_tmp : g_h;

    int n4 = (tid & 31) * 4;
    int kb = tid >> 5;

    float acc[2][8][4];
    #pragma unroll
    for (int mt = 0; mt < 2; mt++)
        #pragma unroll
        for (int nt = 0; nt < 8; nt++)
            #pragma unroll
            for (int q = 0; q < 4; q++) acc[mt][nt][q] = 0.0f;

    #pragma unroll 1
    for (int c = 0; c < 4; c++) {
        int K0 = c * KCH;
        // ---- PREFETCH chunk c operands into registers (before barrier) ----
        float4 va[4];
        {
            const float* Ar = Asrc + (size_t)grow_s * Hh + K0 + sks;
            const float* Gr = g_agg + (size_t)grow_s * Hh + K0 + sks;
            #pragma unroll
            for (int kk = 0; kk < 4; kk++) {
                float4 v = make_float4(0.f, 0.f, 0.f, 0.f);
                if (valid_s) {
                    v = *(const float4*)(Ar + kk * 4);
                    if (phase == 0) {
                        float4 a4 = *(const float4*)(Gr + kk * 4);
                        v.x = fmaf(ep, v.x, a4.x);
                        v.y = fmaf(ep, v.y, a4.y);
                        v.z = fmaf(ep, v.z, a4.z);
                        v.w = fmaf(ep, v.w, a4.w);
                    }
                }
                va[kk] = v;
            }
        }
        float4 wb[4];
        #pragma unroll
        for (int i = 0; i < 4; i++)
            wb[i] = *(const float4*)(W + (size_t)(K0 + kb + i * 8) * Hh + n4);

        __syncthreads();   // previous chunk's smem readers done
        // ---- split & store to smem ----
        #pragma unroll
        for (int kk = 0; kk < 4; kk++) {
            float4 hi, lo;
            split_tf32(va[kk].x, hi.x, lo.x);
            split_tf32(va[kk].y, hi.y, lo.y);
            split_tf32(va[kk].z, hi.z, lo.z);
            split_tf32(va[kk].w, hi.w, lo.w);
            *(float4*)&Ahs[sr * PADA + sks + kk * 4] = hi;
            *(float4*)&Als[sr * PADA + sks + kk * 4] = lo;
        }
        #pragma unroll
        for (int i = 0; i < 4; i++) {
            int kk = kb + i * 8;
            float4 hi, lo;
            split_tf32(wb[i].x, hi.x, lo.x);
            split_tf32(wb[i].y, hi.y, lo.y);
            split_tf32(wb[i].z, hi.z, lo.z);
            split_tf32(wb[i].w, hi.w, lo.w);
            *(float4*)&Bhs[kk * PADB + n4] = hi;
            *(float4*)&Bls[kk * PADB + n4] = lo;
        }
        __syncthreads();
        // ---- compute ----
        #pragma unroll
        for (int k8 = 0; k8 < 4; k8++) {
            uint32_t ah[2][4], al[2][4];
            #pragma unroll
            for (int mt = 0; mt < 2; mt++) {
                int r = m_block * 32 + mt * 16 + g2;
                int col = k8 * 8 + t4;
                ah[mt][0] = __float_as_uint(Ahs[r * PADA + col]);
                ah[mt][1] = __float_as_uint(Ahs[(r + 8) * PADA + col]);
                ah[mt][2] = __float_as_uint(Ahs[r * PADA + col + 4]);
                ah[mt][3] = __float_as_uint(Ahs[(r + 8) * PADA + col + 4]);
                al[mt][0] = __float_as_uint(Als[r * PADA + col]);
                al[mt][1] = __float_as_uint(Als[(r + 8) * PADA + col]);
                al[mt][2] = __float_as_uint(Als[r * PADA + col + 4]);
                al[mt][3] = __float_as_uint(Als[(r + 8) * PADA + col + 4]);
            }
            #pragma unroll
            for (int nt = 0; nt < 8; nt++) {
                int bn = n_block * 64 + nt * 8 + g2;
                int bk = k8 * 8 + t4;
                uint32_t bh0 = __float_as_uint(Bhs[bk * PADB + bn]);
                uint32_t bh1 = __float_as_uint(Bhs[(bk + 4) * PADB + bn]);
                uint32_t bl0 = __float_as_uint(Bls[bk * PADB + bn]);
                uint32_t bl1 = __float_as_uint(Bls[(bk + 4) * PADB + bn]);
                #pragma unroll
                for (int mt = 0; mt < 2; mt++) {
                    MMA_TF32(acc[mt][nt], ah[mt], bh0, bh1);
                    MMA_TF32(acc[mt][nt], al[mt], bh0, bh1);
                    MMA_TF32(acc[mt][nt], ah[mt], bl0, bl1);
                }
            }
        }
    }

    // ---- epilogue ----
    float* Cp = phase ? g_h : g_tmp;
    int do_relu = (phase == 0);
    #pragma unroll
    for (int mt = 0; mt < 2; mt++) {
        int r_lo = row0 + m_block * 32 + mt * 16 + g2;
        int r_hi = r_lo + 8;
        #pragma unroll
        for (int nt = 0; nt < 8; nt++) {
            int cc = n_block * 64 + nt * 8 + t4 * 2;
            float b0 = sbias[cc], b1 = sbias[cc + 1];
            float2 o0 = make_float2(acc[mt][nt][0] + b0, acc[mt][nt][1] + b1);
            float2 o1 = make_float2(acc[mt][nt][2] + b0, acc[mt][nt][3] + b1);
            if (do_relu) {
                o0.x = fmaxf(o0.x, 0.f); o0.y = fmaxf(o0.y, 0.f);
                o1.x = fmaxf(o1.x, 0.f); o1.y = fmaxf(o1.y, 0.f);
            }
            if (r_lo < Nn) {
                *(float2*)(Cp + (size_t)r_lo * Hh + cc) = o0;
                if (C2) *(float2*)(C2 + (size_t)r_lo * (Ll * Hh) + c2off + cc) = o0;
            }
            if (r_hi < Nn) {
                *(float2*)(Cp + (size_t)r_hi * Hh + cc) = o1;
                if (C2) *(float2*)(C2 + (size_t)r_hi * (Ll * Hh) + c2off + cc) = o1;
            }
        }
    }
}

// ---------------- vt: parallel partial sums (g_vt pre-zeroed) ---------------
__global__ void k_vtadd(const int* __restrict__ batch) {
    int row0 = blockIdx.x * 128;
    int c = threadIdx.x;
    int end = row0 + 128; if (end > Nn) end = Nn;
    if (row0 >= Nn) return;
    int gfirst = __ldg(batch + row0);
    int glast  = __ldg(batch + end - 1);
    if (gfirst == glast) {
        float acc = 0.0f;
        #pragma unroll 4
        for (int n = row0; n < end; n++) acc += g_h[(size_t)n * Hh + c];
        atomicAdd(&g_vt[gfirst * Hh + c], acc);
    } else {
        float acc = 0.0f;
        int cur = gfirst;
        for (int n = row0; n < end; n++) {
            int g = __ldg(batch + n);
            if (g != cur) {
                atomicAdd(&g_vt[cur * Hh + c], acc);
                cur = g; acc = 0.0f;
            }
            acc += g_h[(size_t)n * Hh + c];
        }
        atomicAdd(&g_vt[cur * Hh + c], acc);
    }
}

// ---------------- virtual-node two-layer MLP (vt + vn folded in) ------------
__global__ void k_vnmlp(const float* __restrict__ W1, const float* __restrict__ b1,
                        const float* __restrict__ W2, const float* __restrict__ b2) {
    __shared__ float vrow[128];
    __shared__ float trow[128];
    int g = blockIdx.x, c = threadIdx.x;
    vrow[c] = g_vt[g * Hh + c] + g_vn[g * Hh + c];
    __syncthreads();
    float acc = __ldg(b1 + c);
    #pragma unroll 8
    for (int k = 0; k < 128; k++) acc = fmaf(vrow[k], __ldg(W1 + k * 128 + c), acc);
    trow[c] = fmaxf(acc, 0.0f);
    __syncthreads();
    float acc2 = __ldg(b2 + c);
    #pragma unroll 8
    for (int k = 0; k < 128; k++) acc2 = fmaf(trow[k], __ldg(W2 + k * 128 + c), acc2);
    g_vn[g * Hh + c] = fmaxf(acc2, 0.0f);
}

// ---------------- launcher ---------------------------------------------------
extern "C" void kernel_launch(void* const* d_in, const int* in_sizes, int n_in,
                              void* d_out, int out_size) {
    const float* x         = (const float*)d_in[0];
    const float* edge_attr = (const float*)d_in[1];
    const float* conv_W1   = (const float*)d_in[2];
    const float* conv_b1   = (const float*)d_in[3];
    const float* conv_W2   = (const float*)d_in[4];
    const float* conv_b2   = (const float*)d_in[5];
    const float* conv_eps  = (const float*)d_in[6];
    const float* edge_W    = (const float*)d_in[7];
    const float* edge_b    = (const float*)d_in[8];
    const float* vn_W1     = (const float*)d_in[9];
    const float* vn_b1     = (const float*)d_in[10];
    const float* vn_W2     = (const float*)d_in[11];
    const float* vn_b2     = (const float*)d_in[12];
    const float* vn_emb    = (const float*)d_in[13];
    const int*   edge_index= (const int*)d_in[14];
    const int*   batch     = (const int*)d_in[15];
    float* out = (float*)d_out;

    (void)in_sizes; (void)n_in; (void)out_size;

    void* p_deg = nullptr;
    void* p_vt  = nullptr;
    cudaGetSymbolAddress(&p_deg, g_deg);
    cudaGetSymbolAddress(&p_vt, g_vt);

    const int smem_bytes =
        (2 * 128 * PADA + 2 * KCH * PADB) * (int)sizeof(float);
    cudaFuncSetAttribute(k_gemm, cudaFuncAttributeMaxDynamicSharedMemorySize,
                         smem_bytes);

    // ---- CSR build ----
    cudaMemsetAsync(p_deg, 0, Nn * sizeof(int), 0);
    k_deg<<<(Ee + 255) / 256, 256>>>(edge_index + Ee);
    k_scan1<<<NB, 256>>>(vn_emb);
    k_scan2<<<1, 256>>>();
    k_scan3<<<NB, 256>>>();
    k_scatter<<<(Ee + 255) / 256, 256>>>(edge_index, edge_attr);

    const int agg_grid  = (Nn * 32 + 255) / 256;
    const int gemm_grid = (Nn + 127) / 128;

    for (int i = 0; i < Ll; i++) {
        k_addvn<<<(Nn * 32 + 255) / 256, 256>>>(x, batch, i == 0 ? 1 : 0);
        k_agg<<<agg_grid, 256>>>(edge_W + i * Hh, edge_b + i * Hh);
        k_gemm<<<gemm_grid, 256, smem_bytes>>>(0, conv_eps + i,
                                               conv_W1 + (size_t)i * Hh * Hh,
                                               conv_b1 + i * Hh, nullptr, 0);
        k_gemm<<<gemm_grid, 256, smem_bytes>>>(1, conv_eps + i,
                                               conv_W2 + (size_t)i * Hh * Hh,
                                               conv_b2 + i * Hh, out, i * Hh);
        if (i < Ll - 1) {
            cudaMemsetAsync(p_vt, 0, Gg * Hh * sizeof(float), 0);
            k_vtadd<<<gemm_grid, 128>>>(batch);
            k_vnmlp<<<Gg, Hh>>>(vn_W1 + (size_t)i * Hh * Hh, vn_b1 + i * Hh,
                                vn_W2 + (size_t)i * Hh * Hh, vn_b2 + i * Hh);
        }
    }
}

// round 15
// speedup vs baseline: 1.3997x; 1.0240x over previous
#include <cuda_runtime.h>
#include <cstdint>

#define Nn 50000
#define Ee 800000
#define Hh 128
#define Ll 4
#define Gg 64
#define NB 196   // (Nn+255)/256 scan blocks
#define SCAT_BLOCKS ((Ee + 255) / 256)
#define ADDVN_BLOCKS ((Nn * 32 + 255) / 256)

// ---------------- scratch (device globals; no allocation allowed) ----------
__device__ float  g_h[(size_t)Nn * Hh];    // node features (vn-added / post-MLP)
__device__ float  g_tmp[(size_t)Nn * Hh];  // MLP intermediate
__device__ float  g_agg[(size_t)Nn * Hh];  // mean-aggregated messages
__device__ float  g_invdeg[Nn];
__device__ int    g_deg[Nn];               // zero-init; re-zeroed by scan3
__device__ float  g_vn[Gg * Hh];
__device__ float  g_vt[Gg * Hh];           // zero-init; re-zeroed by vnmlp
__device__ int    g_off[Nn + 1];
__device__ int    g_cursor[Nn];
__device__ int    g_bsum[256];
__device__ float2 g_csr[Ee];               // {src_as_float, attr} grouped by tgt

// ---------------- degree histogram (+ vn init) -------------------------------
__global__ void k_deg(const int* __restrict__ tgt,
                      const float* __restrict__ vn_emb) {
    int e = blockIdx.x * blockDim.x + threadIdx.x;
    if (e < Ee) atomicAdd(&g_deg[__ldg(tgt + e)], 1);
    if (e < Gg * Hh) g_vn[e] = __ldg(vn_emb + (e & (Hh - 1)));
}

// ---------------- scan 1: block sums ----------------------------------------
__global__ void k_scan1() {
    __shared__ int s[256];
    int n = blockIdx.x * 256 + threadIdx.x;
    int d = (n < Nn) ? g_deg[n] : 0;
    s[threadIdx.x] = d;
    __syncthreads();
    for (int off = 128; off > 0; off >>= 1) {
        if (threadIdx.x < off) s[threadIdx.x] += s[threadIdx.x + off];
        __syncthreads();
    }
    if (threadIdx.x == 0) g_bsum[blockIdx.x] = s[0];
}

// ---------------- scan 3: full offsets (scan2 folded in) + deg re-zero ------
__global__ void k_scan3() {
    __shared__ int sb[256];
    __shared__ int s[256];
    int tid = threadIdx.x;
    // block-prefix: every block scans the 196 block sums redundantly
    int bv = (tid < NB) ? g_bsum[tid] : 0;
    sb[tid] = bv;
    __syncthreads();
    for (int off = 1; off < 256; off <<= 1) {
        int t = (tid >= off) ? sb[tid - off] : 0;
        __syncthreads();
        sb[tid] += t;
        __syncthreads();
    }
    int bpre = (blockIdx.x > 0) ? sb[blockIdx.x - 1] : 0;
    // intra-block scan of degrees
    int n = blockIdx.x * 256 + tid;
    int d = (n < Nn) ? g_deg[n] : 0;
    s[tid] = d;
    __syncthreads();
    for (int off = 1; off < 256; off <<= 1) {
        int t = (tid >= off) ? s[tid - off] : 0;
        __syncthreads();
        s[tid] += t;
        __syncthreads();
    }
    if (n < Nn) {
        int excl = s[tid] - d + bpre;
        g_off[n] = excl;
        g_cursor[n] = excl;
        g_invdeg[n] = 1.0f / (float)(d > 0 ? d : 1);
        g_deg[n] = 0;          // restore invariant for next call
    }
    if (blockIdx.x == 0 && tid == 0) g_off[Nn] = Ee;
}

// ---------------- dual-role: CSR scatter + layer-0 addvn --------------------
__global__ void k_build(const int* __restrict__ ei,
                        const float* __restrict__ eattr,
                        const float* __restrict__ x,
                        const int* __restrict__ batch) {
    if (blockIdx.x < SCAT_BLOCKS) {
        int e = blockIdx.x * blockDim.x + threadIdx.x;
        if (e >= Ee) return;
        int s = __ldg(ei + e);
        int t = __ldg(ei + Ee + e);
        int p = atomicAdd(&g_cursor[t], 1);
        g_csr[p] = make_float2(__int_as_float(s), __ldg(eattr + e));
    } else {
        int i = (blockIdx.x - SCAT_BLOCKS) * blockDim.x + threadIdx.x;
        if (i >= Nn * 32) return;
        int n = i >> 5;
        int q = (i & 31) * 4;
        int b = __ldg(batch + n);
        float4 v = *(const float4*)(x + (size_t)n * Hh + q);
        float4 w = *(const float4*)(g_vn + b * Hh + q);
        v.x += w.x; v.y += w.y; v.z += w.z; v.w += w.w;
        *(float4*)(g_h + (size_t)n * Hh + q) = v;
    }
}

// ---------------- h = h + vn[batch]  (layers 1..L-1) ------------------------
__global__ void k_addvn(const int* __restrict__ batch) {
    int i = blockIdx.x * blockDim.x + threadIdx.x;
    if (i >= Nn * 32) return;
    int n = i >> 5;
    int q = (i & 31) * 4;
    int b = __ldg(batch + n);
    float4 v = *(const float4*)(g_h + (size_t)n * Hh + q);
    float4 w = *(const float4*)(g_vn + b * Hh + q);
    v.x += w.x; v.y += w.y; v.z += w.z; v.w += w.w;
    *(float4*)(g_h + (size_t)n * Hh + q) = v;
}

// ---------------- CSR mean aggregation: one warp per node, unroll 8 ---------
__device__ __forceinline__ void msg_acc(float4& acc, const float4 h4, float a,
                                        const float4 w, const float4 bb) {
    acc.x += fmaxf(h4.x + fmaf(a, w.x, bb.x), 0.0f);
    acc.y += fmaxf(h4.y + fmaf(a, w.y, bb.y), 0.0f);
    acc.z += fmaxf(h4.z + fmaf(a, w.z, bb.z), 0.0f);
    acc.w += fmaxf(h4.w + fmaf(a, w.w, bb.w), 0.0f);
}

__global__ void k_agg(const float* __restrict__ eW,
                      const float* __restrict__ eb) {
    int n = (blockIdx.x * blockDim.x + threadIdx.x) >> 5;
    if (n >= Nn) return;
    int lane = threadIdx.x & 31;
    int q = lane * 4;
    float4 w  = *(const float4*)(eW + q);
    float4 bb = *(const float4*)(eb + q);
    int j0 = g_off[n], j1 = g_off[n + 1];
    float4 acc = make_float4(0.f, 0.f, 0.f, 0.f);
    int j = j0;
    for (; j + 8 <= j1; j += 8) {
        float2 e[8];
        #pragma unroll
        for (int u = 0; u < 8; u++) e[u] = __ldg(&g_csr[j + u]);
        float4 h[8];
        #pragma unroll
        for (int u = 0; u < 8; u++)
            h[u] = *(const float4*)(g_h + (size_t)__float_as_int(e[u].x) * Hh + q);
        #pragma unroll
        for (int u = 0; u < 8; u++) msg_acc(acc, h[u], e[u].y, w, bb);
    }
    for (; j < j1; j++) {
        float2 e0 = __ldg(&g_csr[j]);
        float4 h0 = *(const float4*)(g_h + (size_t)__float_as_int(e0.x) * Hh + q);
        msg_acc(acc, h0, e0.y, w, bb);
    }
    float idg = g_invdeg[n];
    acc.x *= idg; acc.y *= idg; acc.z *= idg; acc.w *= idg;
    *(float4*)(g_agg + (size_t)n * Hh + q) = acc;
}

// ================= 3xTF32 split GEMM via mma.sync ===========================
#define KCH  32
#define PADA 36    // conflict-free A frag LDS
#define PADB 136   // conflict-free B frag LDS

__device__ __forceinline__ uint32_t to_tf32(float z) {
    uint32_t h;
    asm("cvt.rna.tf32.f32 %0, %1;" : "=r"(h) : "f"(z));
    return h;
}
__device__ __forceinline__ void split_tf32(float z, float& hi, float& lo) {
    uint32_t h = to_tf32(z);
    hi = __uint_as_float(h);
    lo = __uint_as_float(to_tf32(z - hi));
}

#define MMA_TF32(d, a, b0_, b1_) \
    asm volatile("mma.sync.aligned.m16n8k8.row.col.f32.tf32.tf32.f32 " \
        "{%0,%1,%2,%3}, {%4,%5,%6,%7}, {%8,%9}, {%0,%1,%2,%3};" \
        : "+f"((d)[0]), "+f"((d)[1]), "+f"((d)[2]), "+f"((d)[3]) \
        : "r"((a)[0]), "r"((a)[1]), "r"((a)[2]), "r"((a)[3]), \
          "r"(b0_), "r"(b1_))

__global__ void __launch_bounds__(256, 2)
k_gemm(int phase, const float* __restrict__ epsPtr,
       const float* __restrict__ W, const float* __restrict__ bias,
       float* __restrict__ C2, int c2off) {
    extern __shared__ float sm[];
    float* Ahs = sm;                       // [128][PADA]
    float* Als = Ahs + 128 * PADA;
    float* Bhs = Als + 128 * PADA;         // [KCH][PADB]
    float* Bls = Bhs + KCH * PADB;
    __shared__ float sbias[128];

    int tid = threadIdx.x;
    if (tid < 128) sbias[tid] = __ldg(bias + tid);

    int row0 = blockIdx.x * 128;
    int warp = tid >> 5, lane = tid & 31;
    int m_block = warp >> 1;
    int n_block = warp & 1;
    int g2 = lane >> 2, t4 = lane & 3;

    int sr = tid >> 1;
    int sks = (tid & 1) * 16;
    int grow_s = row0 + sr;
    bool valid_s = grow_s < Nn;
    float ep = 1.0f;
    if (phase == 0) ep = 1.0f + __ldg(epsPtr);
    const float* Asrc = phase ? g_tmp : g_h;

    int n4 = (tid & 31) * 4;
    int kb = tid >> 5;

    float acc[2][8][4];
    #pragma unroll
    for (int mt = 0; mt < 2; mt++)
        #pragma unroll
        for (int nt = 0; nt < 8; nt++)
            #pragma unroll
            for (int q = 0; q < 4; q++) acc[mt][nt][q] = 0.0f;

    #pragma unroll 1
    for (int c = 0; c < 4; c++) {
        int K0 = c * KCH;
        // ---- PREFETCH chunk c operands into registers (before barrier) ----
        float4 va[4];
        {
            const float* Ar = Asrc + (size_t)grow_s * Hh + K0 + sks;
            const float* Gr = g_agg + (size_t)grow_s * Hh + K0 + sks;
            #pragma unroll
            for (int kk = 0; kk < 4; kk++) {
                float4 v = make_float4(0.f, 0.f, 0.f, 0.f);
                if (valid_s) {
                    v = *(const float4*)(Ar + kk * 4);
                    if (phase == 0) {
                        float4 a4 = *(const float4*)(Gr + kk * 4);
                        v.x = fmaf(ep, v.x, a4.x);
                        v.y = fmaf(ep, v.y, a4.y);
                        v.z = fmaf(ep, v.z, a4.z);
                        v.w = fmaf(ep, v.w, a4.w);
                    }
                }
                va[kk] = v;
            }
        }
        float4 wb[4];
        #pragma unroll
        for (int i = 0; i < 4; i++)
            wb[i] = *(const float4*)(W + (size_t)(K0 + kb + i * 8) * Hh + n4);

        __syncthreads();   // previous chunk's smem readers done
        // ---- split & store to smem ----
        #pragma unroll
        for (int kk = 0; kk < 4; kk++) {
            float4 hi, lo;
            split_tf32(va[kk].x, hi.x, lo.x);
            split_tf32(va[kk].y, hi.y, lo.y);
            split_tf32(va[kk].z, hi.z, lo.z);
            split_tf32(va[kk].w, hi.w, lo.w);
            *(float4*)&Ahs[sr * PADA + sks + kk * 4] = hi;
            *(float4*)&Als[sr * PADA + sks + kk * 4] = lo;
        }
        #pragma unroll
        for (int i = 0; i < 4; i++) {
            int kk = kb + i * 8;
            float4 hi, lo;
            split_tf32(wb[i].x, hi.x, lo.x);
            split_tf32(wb[i].y, hi.y, lo.y);
            split_tf32(wb[i].z, hi.z, lo.z);
            split_tf32(wb[i].w, hi.w, lo.w);
            *(float4*)&Bhs[kk * PADB + n4] = hi;
            *(float4*)&Bls[kk * PADB + n4] = lo;
        }
        __syncthreads();
        // ---- compute ----
        #pragma unroll
        for (int k8 = 0; k8 < 4; k8++) {
            uint32_t ah[2][4], al[2][4];
            #pragma unroll
            for (int mt = 0; mt < 2; mt++) {
                int r = m_block * 32 + mt * 16 + g2;
                int col = k8 * 8 + t4;
                ah[mt][0] = __float_as_uint(Ahs[r * PADA + col]);
                ah[mt][1] = __float_as_uint(Ahs[(r + 8) * PADA + col]);
                ah[mt][2] = __float_as_uint(Ahs[r * PADA + col + 4]);
                ah[mt][3] = __float_as_uint(Ahs[(r + 8) * PADA + col + 4]);
                al[mt][0] = __float_as_uint(Als[r * PADA + col]);
                al[mt][1] = __float_as_uint(Als[(r + 8) * PADA + col]);
                al[mt][2] = __float_as_uint(Als[r * PADA + col + 4]);
                al[mt][3] = __float_as_uint(Als[(r + 8) * PADA + col + 4]);
            }
            #pragma unroll
            for (int nt = 0; nt < 8; nt++) {
                int bn = n_block * 64 + nt * 8 + g2;
                int bk = k8 * 8 + t4;
                uint32_t bh0 = __float_as_uint(Bhs[bk * PADB + bn]);
                uint32_t bh1 = __float_as_uint(Bhs[(bk + 4) * PADB + bn]);
                uint32_t bl0 = __float_as_uint(Bls[bk * PADB + bn]);
                uint32_t bl1 = __float_as_uint(Bls[(bk + 4) * PADB + bn]);
                #pragma unroll
                for (int mt = 0; mt < 2; mt++) {
                    MMA_TF32(acc[mt][nt], ah[mt], bh0, bh1);
                    MMA_TF32(acc[mt][nt], al[mt], bh0, bh1);
                    MMA_TF32(acc[mt][nt], ah[mt], bl0, bl1);
                }
            }
        }
    }

    // ---- epilogue ----
    float* Cp = phase ? g_h : g_tmp;
    int do_relu = (phase == 0);
    #pragma unroll
    for (int mt = 0; mt < 2; mt++) {
        int r_lo = row0 + m_block * 32 + mt * 16 + g2;
        int r_hi = r_lo + 8;
        #pragma unroll
        for (int nt = 0; nt < 8; nt++) {
            int cc = n_block * 64 + nt * 8 + t4 * 2;
            float b0 = sbias[cc], b1 = sbias[cc + 1];
            float2 o0 = make_float2(acc[mt][nt][0] + b0, acc[mt][nt][1] + b1);
            float2 o1 = make_float2(acc[mt][nt][2] + b0, acc[mt][nt][3] + b1);
            if (do_relu) {
                o0.x = fmaxf(o0.x, 0.f); o0.y = fmaxf(o0.y, 0.f);
                o1.x = fmaxf(o1.x, 0.f); o1.y = fmaxf(o1.y, 0.f);
            }
            if (r_lo < Nn) {
                *(float2*)(Cp + (size_t)r_lo * Hh + cc) = o0;
                if (C2) *(float2*)(C2 + (size_t)r_lo * (Ll * Hh) + c2off + cc) = o0;
            }
            if (r_hi < Nn) {
                *(float2*)(Cp + (size_t)r_hi * Hh + cc) = o1;
                if (C2) *(float2*)(C2 + (size_t)r_hi * (Ll * Hh) + c2off + cc) = o1;
            }
        }
    }
}

// ---------------- vt: parallel partial sums (g_vt zero by invariant) --------
__global__ void k_vtadd(const int* __restrict__ batch) {
    int row0 = blockIdx.x * 128;
    int c = threadIdx.x;
    int end = row0 + 128; if (end > Nn) end = Nn;
    if (row0 >= Nn) return;
    int gfirst = __ldg(batch + row0);
    int glast  = __ldg(batch + end - 1);
    if (gfirst == glast) {
        float acc = 0.0f;
        #pragma unroll 4
        for (int n = row0; n < end; n++) acc += g_h[(size_t)n * Hh + c];
        atomicAdd(&g_vt[gfirst * Hh + c], acc);
    } else {
        float acc = 0.0f;
        int cur = gfirst;
        for (int n = row0; n < end; n++) {
            int g = __ldg(batch + n);
            if (g != cur) {
                atomicAdd(&g_vt[cur * Hh + c], acc);
                cur = g; acc = 0.0f;
            }
            acc += g_h[(size_t)n * Hh + c];
        }
        atomicAdd(&g_vt[cur * Hh + c], acc);
    }
}

// ---------------- virtual-node MLP (vt consumed + re-zeroed) ----------------
__global__ void k_vnmlp(const float* __restrict__ W1, const float* __restrict__ b1,
                        const float* __restrict__ W2, const float* __restrict__ b2) {
    __shared__ float vrow[128];
    __shared__ float trow[128];
    int g = blockIdx.x, c = threadIdx.x;
    vrow[c] = g_vt[g * Hh + c] + g_vn[g * Hh + c];
    g_vt[g * Hh + c] = 0.0f;     // restore invariant for next use
    __syncthreads();
    float acc = __ldg(b1 + c);
    #pragma unroll 8
    for (int k = 0; k < 128; k++) acc = fmaf(vrow[k], __ldg(W1 + k * 128 + c), acc);
    trow[c] = fmaxf(acc, 0.0f);
    __syncthreads();
    float acc2 = __ldg(b2 + c);
    #pragma unroll 8
    for (int k = 0; k < 128; k++) acc2 = fmaf(trow[k], __ldg(W2 + k * 128 + c), acc2);
    g_vn[g * Hh + c] = fmaxf(acc2, 0.0f);
}

// ---------------- launcher ---------------------------------------------------
extern "C" void kernel_launch(void* const* d_in, const int* in_sizes, int n_in,
                              void* d_out, int out_size) {
    const float* x         = (const float*)d_in[0];
    const float* edge_attr = (const float*)d_in[1];
    const float* conv_W1   = (const float*)d_in[2];
    const float* conv_b1   = (const float*)d_in[3];
    const float* conv_W2   = (const float*)d_in[4];
    const float* conv_b2   = (const float*)d_in[5];
    const float* conv_eps  = (const float*)d_in[6];
    const float* edge_W    = (const float*)d_in[7];
    const float* edge_b    = (const float*)d_in[8];
    const float* vn_W1     = (const float*)d_in[9];
    const float* vn_b1     = (const float*)d_in[10];
    const float* vn_W2     = (const float*)d_in[11];
    const float* vn_b2     = (const float*)d_in[12];
    const float* vn_emb    = (const float*)d_in[13];
    const int*   edge_index= (const int*)d_in[14];
    const int*   batch     = (const int*)d_in[15];
    float* out = (float*)d_out;

    (void)in_sizes; (void)n_in; (void)out_size;

    const int smem_bytes =
        (2 * 128 * PADA + 2 * KCH * PADB) * (int)sizeof(float);
    cudaFuncSetAttribute(k_gemm, cudaFuncAttributeMaxDynamicSharedMemorySize,
                         smem_bytes);

    // ---- CSR build (g_deg zero by invariant; scan3 re-zeros it) ----
    k_deg<<<SCAT_BLOCKS, 256>>>(edge_index + Ee, vn_emb);
    k_scan1<<<NB, 256>>>();
    k_scan3<<<NB, 256>>>();
    k_build<<<SCAT_BLOCKS + ADDVN_BLOCKS, 256>>>(edge_index, edge_attr, x, batch);

    const int agg_grid  = (Nn * 32 + 255) / 256;
    const int gemm_grid = (Nn + 127) / 128;

    for (int i = 0; i < Ll; i++) {
        if (i > 0) k_addvn<<<ADDVN_BLOCKS, 256>>>(batch);
        k_agg<<<agg_grid, 256>>>(edge_W + i * Hh, edge_b + i * Hh);
        k_gemm<<<gemm_grid, 256, smem_bytes>>>(0, conv_eps + i,
                                               conv_W1 + (size_t)i * Hh * Hh,
                                               conv_b1 + i * Hh, nullptr, 0);
        k_gemm<<<gemm_grid, 256, smem_bytes>>>(1, conv_eps + i,
                                               conv_W2 + (size_t)i * Hh * Hh,
                                               conv_b2 + i * Hh, out, i * Hh);
        if (i < Ll - 1) {
            k_vtadd<<<gemm_grid, 128>>>(batch);
            k_vnmlp<<<Gg, Hh>>>(vn_W1 + (size_t)i * Hh * Hh, vn_b1 + i * Hh,
                                vn_W2 + (size_t)i * Hh * Hh, vn_b2 + i * Hh);
        }
    }
}